// round 1
// baseline (speedup 1.0000x reference)
#include <cuda_runtime.h>
#include <math.h>

#define NB 4
#define TDIM 8
#define LP1 197
#define HH 12
#define DD 64
#define CC 768
#define LL 196
#define NT 28   // NB*(TDIM-1)

// Scratch: head-averaged attention probabilities for each half.
// P[nt][q][k], nt = n*7 + t  (t is the half-local time index 0..6)
__device__ float g_P1[NT * LL * LL];
__device__ float g_P2[NT * LL * LL];

// ---------------------------------------------------------------------------
// Kernel 0: zero P scratch and the full output tensor.
// ---------------------------------------------------------------------------
__global__ void zero_kernel(float* __restrict__ out) {
    size_t stride = (size_t)gridDim.x * blockDim.x;
    size_t i = (size_t)blockIdx.x * blockDim.x + threadIdx.x;
    const size_t np = (size_t)NT * LL * LL;
    for (size_t j = i; j < np; j += stride) { g_P1[j] = 0.f; g_P2[j] = 0.f; }
    const size_t no = (size_t)NB * TDIM * LP1 * CC;
    for (size_t j = i; j < no; j += stride) out[j] = 0.f;
}

// ---------------------------------------------------------------------------
// Kernel 1: attention.  Block = (h, nt, half).  256 threads.
// Computes softmax_k( (q*scale) . k ) for a 196x196 score matrix (one head),
// then atomically accumulates prob/12 into P (head mean).
//
// smem layout (dynamic):
//   ks[64][209]  transposed K tile (stride 209 -> conflict-free col writes/reads)
//   qs[64][65]   transposed Q chunk (49 rows used)
//   sc[49][208]  score chunk (stride 208 -> conflict-free tiled stores)
// ---------------------------------------------------------------------------
#define KS_STRIDE 209
#define QS_STRIDE 65
#define SC_STRIDE 208
#define A_SMEM_FLOATS (64*KS_STRIDE + 64*QS_STRIDE + 49*SC_STRIDE)
#define A_SMEM_BYTES  (A_SMEM_FLOATS * 4)

__global__ __launch_bounds__(256, 2)
void attn_kernel(const float* __restrict__ q, const float* __restrict__ k) {
    extern __shared__ float sm[];
    float* ks = sm;                          // [64][209]
    float* qs = ks + 64 * KS_STRIDE;         // [64][65]
    float* sc = qs + 64 * QS_STRIDE;         // [49][208]

    int h    = blockIdx.x;
    int nt   = blockIdx.y;
    int half = blockIdx.z;
    int n = nt / 7, t = nt - n * 7;
    int tq = (half == 0) ? t + 1 : t;   // half0: q[:,1:], half1: q[:,:-1]
    int tk = (half == 0) ? t : t + 1;   // half0: k[:,:-1], half1: k[:,1:]

    const float* qb = q + ((size_t)(n * TDIM + tq) * LP1 + 1) * (HH * DD) + h * DD;
    const float* kb = k + ((size_t)(n * TDIM + tk) * LP1 + 1) * (HH * DD) + h * DD;
    float* P = ((half == 0) ? g_P1 : g_P2) + (size_t)nt * LL * LL;

    int tid = threadIdx.x;

    // Load K tile transposed: ks[d][kk] = k[kk][d]
    for (int i = tid; i < LL * DD; i += 256) {
        int kk = i >> 6, d = i & 63;
        ks[d * KS_STRIDE + kk] = kb[(size_t)kk * (HH * DD) + d];
    }

    int tx = tid & 15, ty = tid >> 4;
    int wid = tid >> 5, lane = tid & 31;

    for (int chunk = 0; chunk < 4; chunk++) {
        int q0 = chunk * 49;
        __syncthreads();   // (iter 0: ks load done; later: softmax done before reuse)

        // Load Q chunk transposed, pre-scaled: qs[d][qq] = q[q0+qq][d] * 0.125
        for (int i = tid; i < 49 * DD; i += 256) {
            int qq = i >> 6, d = i & 63;
            qs[d * QS_STRIDE + qq] = qb[(size_t)(q0 + qq) * (HH * DD) + d] * 0.125f;
        }
        __syncthreads();

        // 49x196 score GEMM over K=64, 4x13 register tile per thread (16x16 grid)
        float acc[4][13];
        #pragma unroll
        for (int a = 0; a < 4; a++)
            #pragma unroll
            for (int b = 0; b < 13; b++) acc[a][b] = 0.f;

        for (int d = 0; d < 64; d++) {
            float av[4], bv[13];
            #pragma unroll
            for (int a = 0; a < 4; a++) av[a] = qs[d * QS_STRIDE + ty + 16 * a];
            #pragma unroll
            for (int b = 0; b < 13; b++) bv[b] = ks[d * KS_STRIDE + tx + 16 * b];
            #pragma unroll
            for (int a = 0; a < 4; a++)
                #pragma unroll
                for (int b = 0; b < 13; b++) acc[a][b] = fmaf(av[a], bv[b], acc[a][b]);
        }

        #pragma unroll
        for (int a = 0; a < 4; a++) {
            int m = ty + 16 * a;
            if (m < 49) {
                #pragma unroll
                for (int b = 0; b < 13; b++) {
                    int nn = tx + 16 * b;
                    if (nn < LL) sc[m * SC_STRIDE + nn] = acc[a][b];
                }
            }
        }
        __syncthreads();

        // Row softmax (over k), then atomic head-mean accumulate into P.
        for (int r = wid; r < 49; r += 8) {
            float mx = -1e30f;
            for (int c = lane; c < LL; c += 32) mx = fmaxf(mx, sc[r * SC_STRIDE + c]);
            #pragma unroll
            for (int off = 16; off > 0; off >>= 1)
                mx = fmaxf(mx, __shfl_xor_sync(0xffffffffu, mx, off));
            float s = 0.f;
            for (int c = lane; c < LL; c += 32) {
                float e = __expf(sc[r * SC_STRIDE + c] - mx);
                sc[r * SC_STRIDE + c] = e;
                s += e;
            }
            #pragma unroll
            for (int off = 16; off > 0; off >>= 1)
                s += __shfl_xor_sync(0xffffffffu, s, off);
            float inv = (1.f / 12.f) / s;
            float* Pr = P + (size_t)(q0 + r) * LL;
            for (int c = lane; c < LL; c += 32)
                atomicAdd(Pr + c, sc[r * SC_STRIDE + c] * inv);
        }
    }
}

// ---------------------------------------------------------------------------
// Kernel 2: output contraction  out[n,t,q+1,c] (+)= sum_k P[nt][q][k] * w[IDX[q,k]][c]
// Block = (c-tile of 256, q).  256 threads = 8 warps: warp%4 -> n, warp/4 -> c half.
// w rows for this q are gathered once into smem (196x256 fp32 = 200KB) and each
// float4 is reused across all 7 t from registers.  P rows staged t-transposed.
// half==0 (w1): plain store to t+1.  half==1 (w2): read-modify-write at t.
// ---------------------------------------------------------------------------
#define B_SMEM_FLOATS (LL*256 + 4*LL*8)
#define B_SMEM_BYTES  (B_SMEM_FLOATS * 4)

__global__ __launch_bounds__(256, 1)
void out_kernel(const float* __restrict__ w, float* __restrict__ out, int half) {
    extern __shared__ float sm[];
    float4* ws4 = (float4*)sm;          // [196][64] float4  (196 x 256 floats)
    float* ps = sm + LL * 256;          // [4][196*8]  psw[kk*8 + t]

    int qq = blockIdx.y;
    int c0 = blockIdx.x * 256;
    int tid = threadIdx.x;
    int pi = qq / 14, pj = qq - pi * 14;
    const float* P = (half == 0) ? g_P1 : g_P2;

    // Gather w rows: for each k, row IDX[qq][k], this block's 256-column slice.
    for (int i = tid; i < LL * 64; i += 256) {
        int kk = i >> 6, cq = i & 63;
        int ki = kk / 14, kj = kk - ki * 14;
        int idx = (pi - ki + 13) * 27 + (pj - kj + 13);
        ws4[i] = *(const float4*)(w + (size_t)idx * CC + c0 + cq * 4);
    }

    int warp = tid >> 5;
    int lane = tid & 31;
    int n = warp & 3;
    int chalf = warp >> 2;
    int cq = chalf * 32 + lane;
    float* psw = ps + n * (LL * 8);

    // Stage all 7 P rows for (n, qq), transposed so inner loop reads psw[kk*8+t].
    if (chalf == 0) {
        for (int t = 0; t < 7; t++) {
            const float* Pr = P + ((size_t)(n * 7 + t) * LL + qq) * LL;
            for (int kk = lane; kk < LL; kk += 32) psw[kk * 8 + t] = Pr[kk];
        }
    }
    __syncthreads();

    float4 acc[7];
    #pragma unroll
    for (int t = 0; t < 7; t++) acc[t] = make_float4(0.f, 0.f, 0.f, 0.f);

    #pragma unroll 2
    for (int kk = 0; kk < LL; kk++) {
        float4 wv = ws4[kk * 64 + cq];
        #pragma unroll
        for (int t = 0; t < 7; t++) {
            float a = psw[kk * 8 + t];
            acc[t].x = fmaf(a, wv.x, acc[t].x);
            acc[t].y = fmaf(a, wv.y, acc[t].y);
            acc[t].z = fmaf(a, wv.z, acc[t].z);
            acc[t].w = fmaf(a, wv.w, acc[t].w);
        }
    }

    #pragma unroll
    for (int t = 0; t < 7; t++) {
        int tt = (half == 0) ? t + 1 : t;
        float4* o = (float4*)(out + ((size_t)(n * TDIM + tt) * LP1 + qq + 1) * CC + c0) + cq;
        if (half == 0) {
            *o = acc[t];
        } else {
            float4 v = *o;
            v.x += acc[t].x; v.y += acc[t].y; v.z += acc[t].z; v.w += acc[t].w;
            *o = v;
        }
    }
}

// ---------------------------------------------------------------------------
extern "C" void kernel_launch(void* const* d_in, const int* in_sizes, int n_in,
                              void* d_out, int out_size) {
    const float* q  = (const float*)d_in[0];
    const float* k  = (const float*)d_in[1];
    const float* w1 = (const float*)d_in[2];
    const float* w2 = (const float*)d_in[3];
    float* out = (float*)d_out;

    cudaFuncSetAttribute(attn_kernel, cudaFuncAttributeMaxDynamicSharedMemorySize, A_SMEM_BYTES);
    cudaFuncSetAttribute(out_kernel,  cudaFuncAttributeMaxDynamicSharedMemorySize, B_SMEM_BYTES);

    zero_kernel<<<512, 256>>>(out);
    attn_kernel<<<dim3(HH, NT, 2), 256, A_SMEM_BYTES>>>(q, k);
    out_kernel<<<dim3(3, LL), 256, B_SMEM_BYTES>>>(w1, out, 0);
    out_kernel<<<dim3(3, LL), 256, B_SMEM_BYTES>>>(w2, out, 1);
}

// round 2
// speedup vs baseline: 1.2498x; 1.2498x over previous
#include <cuda_runtime.h>
#include <math.h>

#define NB 4
#define TDIM 8
#define LP1 197
#define HH 12
#define DD 64
#define CC 768
#define LL 196
#define NT 28   // NB*(TDIM-1)

typedef unsigned long long u64;

// packed f32x2 helpers (FFMA2 path — only reachable via PTX fma.rn.f32x2)
__device__ __forceinline__ u64 pk2(float lo, float hi) {
    u64 r; asm("mov.b64 %0,{%1,%2};" : "=l"(r) : "f"(lo), "f"(hi)); return r;
}
__device__ __forceinline__ void upk2(u64 v, float& lo, float& hi) {
    asm("mov.b64 {%0,%1},%2;" : "=f"(lo), "=f"(hi) : "l"(v));
}
__device__ __forceinline__ u64 ffma2(u64 a, u64 b, u64 c) {
    u64 d; asm("fma.rn.f32x2 %0,%1,%2,%3;" : "=l"(d) : "l"(a), "l"(b), "l"(c)); return d;
}

// Scratch: head-averaged attention probabilities for each half.
__device__ float g_P1[NT * LL * LL];
__device__ float g_P2[NT * LL * LL];

// ---------------------------------------------------------------------------
// Kernel 0: zero P scratch and the full output tensor.
// ---------------------------------------------------------------------------
__global__ void zero_kernel(float* __restrict__ out) {
    size_t stride = (size_t)gridDim.x * blockDim.x;
    size_t i = (size_t)blockIdx.x * blockDim.x + threadIdx.x;
    const size_t np = (size_t)NT * LL * LL;
    for (size_t j = i; j < np; j += stride) { g_P1[j] = 0.f; g_P2[j] = 0.f; }
    const size_t no = (size_t)NB * TDIM * LP1 * CC;
    for (size_t j = i; j < no; j += stride) out[j] = 0.f;
}

// ---------------------------------------------------------------------------
// Kernel 1: attention.  Block = (h, nt, half).  256 threads, 2 CTAs/SM.
// f32x2-packed 49x196x64 score GEMM (4 rows x 7 column-pairs per thread),
// warp-per-row softmax, atomic head-mean accumulate into P.
// ---------------------------------------------------------------------------
#define KS_STRIDE 210   // even -> 8B-aligned column pairs for LDS.64
#define QS_STRIDE 65
#define SC_STRIDE 208
#define A_SMEM_FLOATS (64*KS_STRIDE + 64*QS_STRIDE + 49*SC_STRIDE)
#define A_SMEM_BYTES  (A_SMEM_FLOATS * 4)

__global__ __launch_bounds__(256, 2)
void attn_kernel(const float* __restrict__ q, const float* __restrict__ k) {
    extern __shared__ float sm[];
    float* ks = sm;                          // [64][210]
    float* qs = ks + 64 * KS_STRIDE;         // [64][65]
    float* sc = qs + 64 * QS_STRIDE;         // [49][208]

    int h    = blockIdx.x;
    int nt   = blockIdx.y;
    int half = blockIdx.z;
    int n = nt / 7, t = nt - n * 7;
    int tq = (half == 0) ? t + 1 : t;
    int tk = (half == 0) ? t : t + 1;

    const float* qb = q + ((size_t)(n * TDIM + tq) * LP1 + 1) * (HH * DD) + h * DD;
    const float* kb = k + ((size_t)(n * TDIM + tk) * LP1 + 1) * (HH * DD) + h * DD;
    float* P = ((half == 0) ? g_P1 : g_P2) + (size_t)nt * LL * LL;

    int tid = threadIdx.x;

    // K tile transposed: ks[d][kk] = k[kk][d]
    for (int i = tid; i < LL * DD; i += 256) {
        int kk = i >> 6, d = i & 63;
        ks[d * KS_STRIDE + kk] = kb[(size_t)kk * (HH * DD) + d];
    }

    int tx = tid & 15, ty = tid >> 4;
    int wid = tid >> 5, lane = tid & 31;

    for (int chunk = 0; chunk < 4; chunk++) {
        int q0 = chunk * 49;
        __syncthreads();

        // Q chunk transposed, pre-scaled
        for (int i = tid; i < 49 * DD; i += 256) {
            int qq = i >> 6, d = i & 63;
            qs[d * QS_STRIDE + qq] = qb[(size_t)(q0 + qq) * (HH * DD) + d] * 0.125f;
        }
        __syncthreads();

        // 49x196 GEMM over K=64: per thread 4 rows x 7 col-pairs, FFMA2
        u64 acc[4][7];
        #pragma unroll
        for (int a = 0; a < 4; a++)
            #pragma unroll
            for (int b = 0; b < 7; b++) acc[a][b] = 0ULL;

        #pragma unroll 4
        for (int d = 0; d < 64; d++) {
            u64 ad[4], bv[7];
            #pragma unroll
            for (int a = 0; a < 4; a++) {
                float av = qs[d * QS_STRIDE + ty + 16 * a];
                ad[a] = pk2(av, av);
            }
            #pragma unroll
            for (int b = 0; b < 7; b++)
                bv[b] = *(const u64*)&ks[d * KS_STRIDE + 2 * tx + 32 * b];
            #pragma unroll
            for (int a = 0; a < 4; a++)
                #pragma unroll
                for (int b = 0; b < 7; b++)
                    acc[a][b] = ffma2(ad[a], bv[b], acc[a][b]);
        }

        #pragma unroll
        for (int a = 0; a < 4; a++) {
            int m = ty + 16 * a;
            if (m < 49) {
                #pragma unroll
                for (int b = 0; b < 7; b++) {
                    int c = 2 * tx + 32 * b;
                    if (c < LL) {
                        float lo, hi; upk2(acc[a][b], lo, hi);
                        float2 v; v.x = lo; v.y = hi;
                        *(float2*)&sc[m * SC_STRIDE + c] = v;
                    }
                }
            }
        }
        __syncthreads();

        // Row softmax + atomic head-mean accumulate
        for (int r = wid; r < 49; r += 8) {
            float mx = -1e30f;
            for (int c = lane; c < LL; c += 32) mx = fmaxf(mx, sc[r * SC_STRIDE + c]);
            #pragma unroll
            for (int off = 16; off > 0; off >>= 1)
                mx = fmaxf(mx, __shfl_xor_sync(0xffffffffu, mx, off));
            float s = 0.f;
            for (int c = lane; c < LL; c += 32) {
                float e = __expf(sc[r * SC_STRIDE + c] - mx);
                sc[r * SC_STRIDE + c] = e;
                s += e;
            }
            #pragma unroll
            for (int off = 16; off > 0; off >>= 1)
                s += __shfl_xor_sync(0xffffffffu, s, off);
            float inv = (1.f / 12.f) / s;
            float* Pr = P + (size_t)(q0 + r) * LL;
            for (int c = lane; c < LL; c += 32)
                atomicAdd(Pr + c, sc[r * SC_STRIDE + c] * inv);
        }
    }
}

// ---------------------------------------------------------------------------
// Kernel 2: out[n,tt,q+1,c] (+)= sum_k P[nt][q][k] * w[IDX[q,k]][c]
// Block = (c-tile 128, q, n-pair).  256 threads, 2 CTAs/SM.
// 8 warps = (n_local: 2) x (k-quarter: 4); each warp holds all 7 t-accumulators
// as 4 f32x2 t-pair registers x 4 c-columns; smem reduction over k-quarters
// reuses the w tile area.  half==0: store to t+1.  half==1: RMW at t.
// ---------------------------------------------------------------------------
#define TC 128
#define B_SMEM_FLOATS (LL*TC + 2*LL*8)
#define B_SMEM_BYTES  (B_SMEM_FLOATS * 4)

__global__ __launch_bounds__(256, 2)
void out_kernel(const float* __restrict__ w, float* __restrict__ out, int half) {
    extern __shared__ float sm[];
    float4* ws4 = (float4*)sm;          // [196][32] float4
    float* ps = sm + LL * TC;           // [2][196*8]

    int qq = blockIdx.y;
    int c0 = blockIdx.x * TC;
    int np = blockIdx.z;                // n pair: n = 2*np + n_local
    int tid = threadIdx.x;
    int pi = qq / 14, pj = qq - pi * 14;
    const float* P = (half == 0) ? g_P1 : g_P2;

    // Gather w rows for this q (this block's 128-column slice)
    for (int i = tid; i < LL * 32; i += 256) {
        int kk = i >> 5, cq = i & 31;
        int ki = kk / 14, kj = kk - ki * 14;
        int idx = (pi - ki + 13) * 27 + (pj - kj + 13);
        ws4[i] = *(const float4*)(w + (size_t)idx * CC + c0 + cq * 4);
    }

    // Stage P rows t-strided: ps[n_l][kk*8 + t], slot 7 zeroed
    #pragma unroll
    for (int r = 0; r < 14; r++) {
        int n_l = r / 7, t = r - n_l * 7;
        if (tid < LL) {
            int n = np * 2 + n_l;
            ps[n_l * (LL * 8) + tid * 8 + t] =
                P[((size_t)(n * 7 + t) * LL + qq) * LL + tid];
        }
    }
    if (tid < LL) { ps[tid * 8 + 7] = 0.f; ps[LL * 8 + tid * 8 + 7] = 0.f; }
    __syncthreads();

    int wid = tid >> 5, lane = tid & 31;
    int n_l = wid >> 2, kq = wid & 3;
    const float* psn = ps + n_l * (LL * 8);

    u64 acc[16];   // acc[tp*4 + c] : f32x2 over t-pair (2tp, 2tp+1), column c
    #pragma unroll
    for (int i = 0; i < 16; i++) acc[i] = 0ULL;

    int k0 = kq * 49;
    #pragma unroll 7
    for (int kk = k0; kk < k0 + 49; kk++) {
        float4 wv = ws4[kk * 32 + lane];
        u64 b0 = pk2(wv.x, wv.x), b1 = pk2(wv.y, wv.y);
        u64 b2 = pk2(wv.z, wv.z), b3 = pk2(wv.w, wv.w);
        const u64* pp = (const u64*)&psn[kk * 8];   // (t0,t1)(t2,t3)(t4,t5)(t6,0)
        u64 p0 = pp[0], p1 = pp[1], p2 = pp[2], p3 = pp[3];
        acc[0]  = ffma2(p0, b0, acc[0]);  acc[1]  = ffma2(p0, b1, acc[1]);
        acc[2]  = ffma2(p0, b2, acc[2]);  acc[3]  = ffma2(p0, b3, acc[3]);
        acc[4]  = ffma2(p1, b0, acc[4]);  acc[5]  = ffma2(p1, b1, acc[5]);
        acc[6]  = ffma2(p1, b2, acc[6]);  acc[7]  = ffma2(p1, b3, acc[7]);
        acc[8]  = ffma2(p2, b0, acc[8]);  acc[9]  = ffma2(p2, b1, acc[9]);
        acc[10] = ffma2(p2, b2, acc[10]); acc[11] = ffma2(p2, b3, acc[11]);
        acc[12] = ffma2(p3, b0, acc[12]); acc[13] = ffma2(p3, b1, acc[13]);
        acc[14] = ffma2(p3, b2, acc[14]); acc[15] = ffma2(p3, b3, acc[15]);
    }

    float a[32];
    #pragma unroll
    for (int i = 0; i < 16; i++) upk2(acc[i], a[2 * i], a[2 * i + 1]);

    // Reduce over k-quarters through smem (reuse the w tile area)
    __syncthreads();   // everyone done reading ws4
    float4* red = ws4;
    if (kq) {
        int base = ((n_l * 3 + (kq - 1)) * 32 + lane) * 8;
        #pragma unroll
        for (int j = 0; j < 8; j++) {
            float4 v; v.x = a[4*j]; v.y = a[4*j+1]; v.z = a[4*j+2]; v.w = a[4*j+3];
            red[base + j] = v;
        }
    }
    __syncthreads();

    if (kq == 0) {
        #pragma unroll
        for (int ww = 0; ww < 3; ww++) {
            int base = ((n_l * 3 + ww) * 32 + lane) * 8;
            #pragma unroll
            for (int j = 0; j < 8; j++) {
                float4 v = red[base + j];
                a[4*j] += v.x; a[4*j+1] += v.y; a[4*j+2] += v.z; a[4*j+3] += v.w;
            }
        }
        int n = np * 2 + n_l;
        #pragma unroll
        for (int t = 0; t < 7; t++) {
            int tp = t >> 1, hi = t & 1;
            float4 o4;
            o4.x = a[(tp * 4 + 0) * 2 + hi];
            o4.y = a[(tp * 4 + 1) * 2 + hi];
            o4.z = a[(tp * 4 + 2) * 2 + hi];
            o4.w = a[(tp * 4 + 3) * 2 + hi];
            int tt = (half == 0) ? t + 1 : t;
            float4* o = (float4*)(out + ((size_t)(n * TDIM + tt) * LP1 + qq + 1) * CC + c0) + lane;
            if (half == 0) {
                *o = o4;
            } else {
                float4 v = *o;
                v.x += o4.x; v.y += o4.y; v.z += o4.z; v.w += o4.w;
                *o = v;
            }
        }
    }
}

// ---------------------------------------------------------------------------
extern "C" void kernel_launch(void* const* d_in, const int* in_sizes, int n_in,
                              void* d_out, int out_size) {
    const float* q  = (const float*)d_in[0];
    const float* k  = (const float*)d_in[1];
    const float* w1 = (const float*)d_in[2];
    const float* w2 = (const float*)d_in[3];
    float* out = (float*)d_out;

    cudaFuncSetAttribute(attn_kernel, cudaFuncAttributeMaxDynamicSharedMemorySize, A_SMEM_BYTES);
    cudaFuncSetAttribute(out_kernel,  cudaFuncAttributeMaxDynamicSharedMemorySize, B_SMEM_BYTES);

    zero_kernel<<<512, 256>>>(out);
    attn_kernel<<<dim3(HH, NT, 2), 256, A_SMEM_BYTES>>>(q, k);
    out_kernel<<<dim3(CC / TC, LL, NB / 2), 256, B_SMEM_BYTES>>>(w1, out, 0);
    out_kernel<<<dim3(CC / TC, LL, NB / 2), 256, B_SMEM_BYTES>>>(w2, out, 1);
}

// round 3
// speedup vs baseline: 1.6525x; 1.3222x over previous
#include <cuda_runtime.h>
#include <math.h>

#define NB 4
#define TDIM 8
#define LP1 197
#define HH 12
#define DD 64
#define CC 768
#define LL 196
#define NT 28   // NB*(TDIM-1)

typedef unsigned long long u64;

__device__ __forceinline__ u64 pk2(float lo, float hi) {
    u64 r; asm("mov.b64 %0,{%1,%2};" : "=l"(r) : "f"(lo), "f"(hi)); return r;
}
__device__ __forceinline__ void upk2(u64 v, float& lo, float& hi) {
    asm("mov.b64 {%0,%1},%2;" : "=f"(lo), "=f"(hi) : "l"(v));
}
__device__ __forceinline__ u64 ffma2(u64 a, u64 b, u64 c) {
    u64 d; asm("fma.rn.f32x2 %0,%1,%2,%3;" : "=l"(d) : "l"(a), "l"(b), "l"(c)); return d;
}
__device__ __forceinline__ u64 fadd2(u64 a, u64 b) {
    u64 d; asm("add.rn.f32x2 %0,%1,%2;" : "=l"(d) : "l"(a), "l"(b)); return d;
}
// vector float2 reduction (sm_90+): halves atomic instruction count
__device__ __forceinline__ void red2(float* p, float a, float b) {
    asm volatile("red.global.add.v2.f32 [%0], {%1,%2};" :: "l"(p), "f"(a), "f"(b) : "memory");
}

// Scratch: head-averaged attention probabilities for each half.
__device__ float g_P1[NT * LL * LL];
__device__ float g_P2[NT * LL * LL];

// ---------------------------------------------------------------------------
// Kernel 0: zero P scratch and the cls (q=0) rows of out.
// (All q>=1 rows of out are fully written by out_kernel, so no RMW/zero needed.)
// ---------------------------------------------------------------------------
__global__ void zero_kernel(float* __restrict__ out) {
    size_t stride = (size_t)gridDim.x * blockDim.x;
    size_t i = (size_t)blockIdx.x * blockDim.x + threadIdx.x;
    const size_t np = (size_t)NT * LL * LL;
    for (size_t j = i; j < np; j += stride) { g_P1[j] = 0.f; g_P2[j] = 0.f; }
    const size_t ncls = (size_t)NB * TDIM * CC;
    for (size_t j = i; j < ncls; j += stride) {
        size_t nt = j / CC, c = j - nt * CC;
        out[(nt * LP1) * CC + c] = 0.f;
    }
}

// ---------------------------------------------------------------------------
// Kernel 1: attention.  Block = (h, nt, half*2+qhalf).  256 threads, 3 CTAs/SM.
// 98 q-rows per block, 2 chunks of 49.  f32x2 GEMM (4 rows x 7 col-pairs /thr),
// REGISTER-RESIDENT softmax: each row is owned by one half-warp (same ty),
// reduced with shfl_xor over 16 lanes.  Head-mean accumulated into P via
// red.global.add.v2.f32.
// ---------------------------------------------------------------------------
#define KS_STRIDE 210
#define QS_STRIDE 65
#define A_SMEM_BYTES ((64*KS_STRIDE + 64*QS_STRIDE) * 4)

__global__ __launch_bounds__(256, 3)
void attn_kernel(const float* __restrict__ q, const float* __restrict__ k) {
    extern __shared__ float sm[];
    float* ks = sm;                          // [64][210]
    float* qs = ks + 64 * KS_STRIDE;         // [64][65]

    int h    = blockIdx.x;
    int nt   = blockIdx.y;
    int half = blockIdx.z >> 1;
    int qh   = blockIdx.z & 1;
    int n = nt / 7, t = nt - n * 7;
    int tq = (half == 0) ? t + 1 : t;
    int tk = (half == 0) ? t : t + 1;

    const float* qb = q + ((size_t)(n * TDIM + tq) * LP1 + 1) * (HH * DD) + h * DD;
    const float* kb = k + ((size_t)(n * TDIM + tk) * LP1 + 1) * (HH * DD) + h * DD;
    float* P = ((half == 0) ? g_P1 : g_P2) + (size_t)nt * LL * LL;

    int tid = threadIdx.x;

    // K tile transposed: ks[d][kk] = k[kk][d]
    for (int i = tid; i < LL * DD; i += 256) {
        int kk = i >> 6, d = i & 63;
        ks[d * KS_STRIDE + kk] = kb[(size_t)kk * (HH * DD) + d];
    }

    int tx = tid & 15, ty = tid >> 4;

    for (int chunk = 0; chunk < 2; chunk++) {
        int q0 = qh * 98 + chunk * 49;
        __syncthreads();   // ks ready (iter0) / qs no longer read (iter1)

        // Q chunk transposed, pre-scaled
        for (int i = tid; i < 49 * DD; i += 256) {
            int qq = i >> 6, d = i & 63;
            qs[d * QS_STRIDE + qq] = qb[(size_t)(q0 + qq) * (HH * DD) + d] * 0.125f;
        }
        __syncthreads();

        u64 acc[4][7];
        #pragma unroll
        for (int a = 0; a < 4; a++)
            #pragma unroll
            for (int b = 0; b < 7; b++) acc[a][b] = 0ULL;

        #pragma unroll 4
        for (int d = 0; d < 64; d++) {
            u64 ad[4], bv[7];
            #pragma unroll
            for (int a = 0; a < 4; a++) {
                float av = qs[d * QS_STRIDE + ty + 16 * a];
                ad[a] = pk2(av, av);
            }
            #pragma unroll
            for (int b = 0; b < 7; b++)
                bv[b] = *(const u64*)&ks[d * KS_STRIDE + 2 * tx + 32 * b];
            #pragma unroll
            for (int a = 0; a < 4; a++)
                #pragma unroll
                for (int b = 0; b < 7; b++)
                    acc[a][b] = ffma2(ad[a], bv[b], acc[a][b]);
        }

        // Register softmax per row (half-warp = same ty owns a row).
        // b=6 pair valid only for tx<2 (cols 192..195).  Rows >= 49 are junk;
        // we still run the shuffles (no divergence) and guard only the store.
        #pragma unroll
        for (int a = 0; a < 4; a++) {
            int r = ty + 16 * a;
            float e[14];
            #pragma unroll
            for (int b = 0; b < 7; b++) upk2(acc[a][b], e[2 * b], e[2 * b + 1]);

            bool v6 = (tx < 2);
            float mx = -1e30f;
            #pragma unroll
            for (int b = 0; b < 6; b++) mx = fmaxf(mx, fmaxf(e[2 * b], e[2 * b + 1]));
            if (v6) mx = fmaxf(mx, fmaxf(e[12], e[13]));
            #pragma unroll
            for (int off = 8; off > 0; off >>= 1)
                mx = fmaxf(mx, __shfl_xor_sync(0xffffffffu, mx, off));

            float s = 0.f;
            #pragma unroll
            for (int b = 0; b < 6; b++) {
                e[2 * b]     = __expf(e[2 * b] - mx);
                e[2 * b + 1] = __expf(e[2 * b + 1] - mx);
                s += e[2 * b] + e[2 * b + 1];
            }
            if (v6) {
                e[12] = __expf(e[12] - mx);
                e[13] = __expf(e[13] - mx);
                s += e[12] + e[13];
            }
            #pragma unroll
            for (int off = 8; off > 0; off >>= 1)
                s += __shfl_xor_sync(0xffffffffu, s, off);

            float inv = (1.f / 12.f) / s;
            if (r < 49) {
                float* Pr = P + (size_t)(q0 + r) * LL + 2 * tx;
                #pragma unroll
                for (int b = 0; b < 6; b++)
                    red2(Pr + 32 * b, e[2 * b] * inv, e[2 * b + 1] * inv);
                if (v6) red2(Pr + 192, e[12] * inv, e[13] * inv);
            }
        }
    }
}

// ---------------------------------------------------------------------------
// Kernel 2 (fused halves): out[n,tt,q+1,c] = sum_k P1[n,tt-1,q,k]*w1[IDX[q,k],c]
//                                          + sum_k P2[n,tt  ,q,k]*w2[IDX[q,k],c]
// Block = (c-tile 64, q, n-pair).  256 threads, 4 CTAs/SM (50KB smem).
// P staged once t-strided (half0 shifted +1, slot0/slot7 zeroed -> all 8 t-slots
// useful).  w gathered in 4 phases (w1/k-lo, w1/k-hi, w2/k-lo, w2/k-hi) into a
// single 98-row tile.  8 warps = 2 n_local x 4 k-quarters; smem reduction; one
// plain store (no RMW, no second launch).
// ---------------------------------------------------------------------------
#define TCo 64
#define WS_FLOATS (98 * TCo)            // 6272
#define PS_FLOATS (2 * LL * 8)          // 3136 per half
#define O_SMEM_BYTES ((WS_FLOATS + 2 * PS_FLOATS) * 4)   // 50176 B

__global__ __launch_bounds__(256, 4)
void out_kernel(const float* __restrict__ w1, const float* __restrict__ w2,
                float* __restrict__ out) {
    extern __shared__ float sm[];
    float* ws  = sm;                    // [98][64]
    float* psA = sm + WS_FLOATS;        // [2][196*8]  half0 (shifted: slot tt = P1[t=tt-1])
    float* psB = psA + PS_FLOATS;       // [2][196*8]  half1 (slot tt = P2[tt], slot7=0)

    int qq = blockIdx.y;
    int c0 = blockIdx.x * TCo;
    int np = blockIdx.z;
    int tid = threadIdx.x;
    int pi = qq / 14, pj = qq - pi * 14;

    // Stage P rows t-strided (both halves, both local n).
    #pragma unroll
    for (int r = 0; r < 14; r++) {
        int n_l = r / 7, t = r - n_l * 7;
        if (tid < LL) {
            int n = np * 2 + n_l;
            size_t base = ((size_t)(n * 7 + t) * LL + qq) * LL + tid;
            psA[n_l * (LL * 8) + tid * 8 + t + 1] = g_P1[base];
            psB[n_l * (LL * 8) + tid * 8 + t]     = g_P2[base];
        }
    }
    if (tid < LL) {
        psA[tid * 8] = 0.f;            psA[LL * 8 + tid * 8] = 0.f;
        psB[tid * 8 + 7] = 0.f;        psB[LL * 8 + tid * 8 + 7] = 0.f;
    }

    int wid = tid >> 5, lane = tid & 31;
    int n_l = wid >> 2, kq = wid & 3;
    // k-quarter split of 98: 25,25,24,24
    int kst = kq * 25 - ((kq > 2) ? (kq - 2) : 0);
    int kcn = 25 - (kq >= 2 ? 1 : 0);

    u64 acc[8];   // [tp][cpart]: tp = tt-pair 0..3, cpart = which of lane's 2 cols
    #pragma unroll
    for (int i = 0; i < 8; i++) acc[i] = 0ULL;

    #pragma unroll
    for (int ph = 0; ph < 4; ph++) {
        const float* w = (ph < 2) ? w1 : w2;
        const float* ps = ((ph < 2) ? psA : psB) + n_l * (LL * 8);
        int kbase = (ph & 1) * 98;

        __syncthreads();   // ws free to overwrite (and ps staged, for ph=0)
        // Gather 98 w rows (this block's 64-col slice): 16 float4 per row.
        for (int i = tid; i < 98 * 16; i += 256) {
            int kk = i >> 4, cq = i & 15;
            int kg = kbase + kk;
            int ki = kg / 14, kj = kg - ki * 14;
            int idx = (pi - ki + 13) * 27 + (pj - kj + 13);
            *(float4*)&ws[kk * TCo + cq * 4] =
                *(const float4*)(w + (size_t)idx * CC + c0 + cq * 4);
        }
        __syncthreads();

        #pragma unroll 5
        for (int kl = kst; kl < kst + kcn; kl++) {
            float2 wv = *(const float2*)&ws[kl * TCo + 2 * lane];
            u64 b0 = pk2(wv.x, wv.x), b1 = pk2(wv.y, wv.y);
            const u64* pp = (const u64*)&ps[(kbase + kl) * 8];
            u64 p0 = pp[0], p1 = pp[1], p2 = pp[2], p3 = pp[3];
            acc[0] = ffma2(p0, b0, acc[0]);  acc[1] = ffma2(p0, b1, acc[1]);
            acc[2] = ffma2(p1, b0, acc[2]);  acc[3] = ffma2(p1, b1, acc[3]);
            acc[4] = ffma2(p2, b0, acc[4]);  acc[5] = ffma2(p2, b1, acc[5]);
            acc[6] = ffma2(p3, b0, acc[6]);  acc[7] = ffma2(p3, b1, acc[7]);
        }
    }

    // Cross-k-quarter reduction through smem (reuse ws area).
    __syncthreads();
    u64* red = (u64*)ws;
    if (kq) {
        int base = ((n_l * 3 + (kq - 1)) * 32 + lane) * 8;
        #pragma unroll
        for (int j = 0; j < 8; j++) red[base + j] = acc[j];
    }
    __syncthreads();

    if (kq == 0) {
        #pragma unroll
        for (int ww = 0; ww < 3; ww++) {
            int base = ((n_l * 3 + ww) * 32 + lane) * 8;
            #pragma unroll
            for (int j = 0; j < 8; j++) acc[j] = fadd2(acc[j], red[base + j]);
        }
        int n = np * 2 + n_l;
        float a[16];
        #pragma unroll
        for (int i = 0; i < 8; i++) upk2(acc[i], a[2 * i], a[2 * i + 1]);
        #pragma unroll
        for (int tt = 0; tt < 8; tt++) {
            int tp = tt >> 1, hi = tt & 1;
            float2 o2;
            o2.x = a[(tp * 2 + 0) * 2 + hi];   // lane col 2*lane
            o2.y = a[(tp * 2 + 1) * 2 + hi];   // lane col 2*lane+1
            *(float2*)(out + ((size_t)(n * TDIM + tt) * LP1 + qq + 1) * CC
                       + c0 + 2 * lane) = o2;
        }
    }
}

// ---------------------------------------------------------------------------
extern "C" void kernel_launch(void* const* d_in, const int* in_sizes, int n_in,
                              void* d_out, int out_size) {
    const float* q  = (const float*)d_in[0];
    const float* k  = (const float*)d_in[1];
    const float* w1 = (const float*)d_in[2];
    const float* w2 = (const float*)d_in[3];
    float* out = (float*)d_out;

    cudaFuncSetAttribute(attn_kernel, cudaFuncAttributeMaxDynamicSharedMemorySize, A_SMEM_BYTES);
    cudaFuncSetAttribute(out_kernel,  cudaFuncAttributeMaxDynamicSharedMemorySize, O_SMEM_BYTES);

    zero_kernel<<<512, 256>>>(out);
    attn_kernel<<<dim3(HH, NT, 4), 256, A_SMEM_BYTES>>>(q, k);
    out_kernel<<<dim3(CC / TCo, LL, NB / 2), 256, O_SMEM_BYTES>>>(w1, w2, out);
}

// round 4
// speedup vs baseline: 1.6577x; 1.0031x over previous
#include <cuda_runtime.h>
#include <math.h>

#define NB 4
#define TDIM 8
#define LP1 197
#define HH 12
#define DD 64
#define CC 768
#define LL 196
#define NT 28   // NB*(TDIM-1)

typedef unsigned long long u64;

__device__ __forceinline__ u64 pk2(float lo, float hi) {
    u64 r; asm("mov.b64 %0,{%1,%2};" : "=l"(r) : "f"(lo), "f"(hi)); return r;
}
__device__ __forceinline__ void upk2(u64 v, float& lo, float& hi) {
    asm("mov.b64 {%0,%1},%2;" : "=f"(lo), "=f"(hi) : "l"(v));
}
__device__ __forceinline__ u64 ffma2(u64 a, u64 b, u64 c) {
    u64 d; asm("fma.rn.f32x2 %0,%1,%2,%3;" : "=l"(d) : "l"(a), "l"(b), "l"(c)); return d;
}
__device__ __forceinline__ u64 fadd2(u64 a, u64 b) {
    u64 d; asm("add.rn.f32x2 %0,%1,%2;" : "=l"(d) : "l"(a), "l"(b)); return d;
}
// vector float2 reduction (sm_90+): halves atomic instruction count
__device__ __forceinline__ void red2(float* p, float a, float b) {
    asm volatile("red.global.add.v2.f32 [%0], {%1,%2};" :: "l"(p), "f"(a), "f"(b) : "memory");
}

// Scratch: head-averaged attention probabilities for each half.
__device__ float g_P1[NT * LL * LL];
__device__ float g_P2[NT * LL * LL];

// ---------------------------------------------------------------------------
// Kernel 0: zero P scratch and the cls (q=0) rows of out.
// (All q>=1 rows of out are fully written by out_kernel, so no RMW/zero needed.)
// ---------------------------------------------------------------------------
__global__ void zero_kernel(float* __restrict__ out) {
    size_t stride = (size_t)gridDim.x * blockDim.x;
    size_t i = (size_t)blockIdx.x * blockDim.x + threadIdx.x;
    const size_t np = (size_t)NT * LL * LL;
    for (size_t j = i; j < np; j += stride) { g_P1[j] = 0.f; g_P2[j] = 0.f; }
    const size_t ncls = (size_t)NB * TDIM * CC;
    for (size_t j = i; j < ncls; j += stride) {
        size_t nt = j / CC, c = j - nt * CC;
        out[(nt * LP1) * CC + c] = 0.f;
    }
}

// ---------------------------------------------------------------------------
// Kernel 1: attention.  Block = (h, nt, half*2+qhalf).  256 threads, 3 CTAs/SM.
// 98 q-rows per block, 2 chunks of 49.  f32x2 GEMM (4 rows x 7 col-pairs /thr),
// REGISTER-RESIDENT softmax: each row is owned by one half-warp (same ty),
// reduced with shfl_xor over 16 lanes.  Head-mean accumulated into P via
// red.global.add.v2.f32.
// ---------------------------------------------------------------------------
#define KS_STRIDE 210
#define QS_STRIDE 65
#define A_SMEM_BYTES ((64*KS_STRIDE + 64*QS_STRIDE) * 4)

__global__ __launch_bounds__(256, 3)
void attn_kernel(const float* __restrict__ q, const float* __restrict__ k) {
    extern __shared__ float sm[];
    float* ks = sm;                          // [64][210]
    float* qs = ks + 64 * KS_STRIDE;         // [64][65]

    int h    = blockIdx.x;
    int nt   = blockIdx.y;
    int half = blockIdx.z >> 1;
    int qh   = blockIdx.z & 1;
    int n = nt / 7, t = nt - n * 7;
    int tq = (half == 0) ? t + 1 : t;
    int tk = (half == 0) ? t : t + 1;

    const float* qb = q + ((size_t)(n * TDIM + tq) * LP1 + 1) * (HH * DD) + h * DD;
    const float* kb = k + ((size_t)(n * TDIM + tk) * LP1 + 1) * (HH * DD) + h * DD;
    float* P = ((half == 0) ? g_P1 : g_P2) + (size_t)nt * LL * LL;

    int tid = threadIdx.x;

    // K tile transposed: ks[d][kk] = k[kk][d]
    for (int i = tid; i < LL * DD; i += 256) {
        int kk = i >> 6, d = i & 63;
        ks[d * KS_STRIDE + kk] = kb[(size_t)kk * (HH * DD) + d];
    }

    int tx = tid & 15, ty = tid >> 4;

    for (int chunk = 0; chunk < 2; chunk++) {
        int q0 = qh * 98 + chunk * 49;
        __syncthreads();   // ks ready (iter0) / qs no longer read (iter1)

        // Q chunk transposed, pre-scaled
        for (int i = tid; i < 49 * DD; i += 256) {
            int qq = i >> 6, d = i & 63;
            qs[d * QS_STRIDE + qq] = qb[(size_t)(q0 + qq) * (HH * DD) + d] * 0.125f;
        }
        __syncthreads();

        u64 acc[4][7];
        #pragma unroll
        for (int a = 0; a < 4; a++)
            #pragma unroll
            for (int b = 0; b < 7; b++) acc[a][b] = 0ULL;

        #pragma unroll 4
        for (int d = 0; d < 64; d++) {
            u64 ad[4], bv[7];
            #pragma unroll
            for (int a = 0; a < 4; a++) {
                float av = qs[d * QS_STRIDE + ty + 16 * a];
                ad[a] = pk2(av, av);
            }
            #pragma unroll
            for (int b = 0; b < 7; b++)
                bv[b] = *(const u64*)&ks[d * KS_STRIDE + 2 * tx + 32 * b];
            #pragma unroll
            for (int a = 0; a < 4; a++)
                #pragma unroll
                for (int b = 0; b < 7; b++)
                    acc[a][b] = ffma2(ad[a], bv[b], acc[a][b]);
        }

        // Register softmax per row (half-warp = same ty owns a row).
        // b=6 pair valid only for tx<2 (cols 192..195).  Rows >= 49 are junk;
        // we still run the shuffles (no divergence) and guard only the store.
        #pragma unroll
        for (int a = 0; a < 4; a++) {
            int r = ty + 16 * a;
            float e[14];
            #pragma unroll
            for (int b = 0; b < 7; b++) upk2(acc[a][b], e[2 * b], e[2 * b + 1]);

            bool v6 = (tx < 2);
            float mx = -1e30f;
            #pragma unroll
            for (int b = 0; b < 6; b++) mx = fmaxf(mx, fmaxf(e[2 * b], e[2 * b + 1]));
            if (v6) mx = fmaxf(mx, fmaxf(e[12], e[13]));
            #pragma unroll
            for (int off = 8; off > 0; off >>= 1)
                mx = fmaxf(mx, __shfl_xor_sync(0xffffffffu, mx, off));

            float s = 0.f;
            #pragma unroll
            for (int b = 0; b < 6; b++) {
                e[2 * b]     = __expf(e[2 * b] - mx);
                e[2 * b + 1] = __expf(e[2 * b + 1] - mx);
                s += e[2 * b] + e[2 * b + 1];
            }
            if (v6) {
                e[12] = __expf(e[12] - mx);
                e[13] = __expf(e[13] - mx);
                s += e[12] + e[13];
            }
            #pragma unroll
            for (int off = 8; off > 0; off >>= 1)
                s += __shfl_xor_sync(0xffffffffu, s, off);

            float inv = (1.f / 12.f) / s;
            if (r < 49) {
                float* Pr = P + (size_t)(q0 + r) * LL + 2 * tx;
                #pragma unroll
                for (int b = 0; b < 6; b++)
                    red2(Pr + 32 * b, e[2 * b] * inv, e[2 * b + 1] * inv);
                if (v6) red2(Pr + 192, e[12] * inv, e[13] * inv);
            }
        }
    }
}

// ---------------------------------------------------------------------------
// Kernel 2 (fused halves): out[n,tt,q+1,c] = sum_k P1[n,tt-1,q,k]*w1[IDX[q,k],c]
//                                          + sum_k P2[n,tt  ,q,k]*w2[IDX[q,k],c]
// Block = (c-tile 64, q, n-pair).  256 threads, 4 CTAs/SM (50KB smem).
// P staged once t-strided (half0 shifted +1, slot0/slot7 zeroed -> all 8 t-slots
// useful).  w gathered in 4 phases (w1/k-lo, w1/k-hi, w2/k-lo, w2/k-hi) into a
// single 98-row tile.  8 warps = 2 n_local x 4 k-quarters; smem reduction; one
// plain store (no RMW, no second launch).
// ---------------------------------------------------------------------------
#define TCo 64
#define WS_FLOATS (98 * TCo)            // 6272
#define PS_FLOATS (2 * LL * 8)          // 3136 per half
#define O_SMEM_BYTES ((WS_FLOATS + 2 * PS_FLOATS) * 4)   // 50176 B

__global__ __launch_bounds__(256, 4)
void out_kernel(const float* __restrict__ w1, const float* __restrict__ w2,
                float* __restrict__ out) {
    extern __shared__ float sm[];
    float* ws  = sm;                    // [98][64]
    float* psA = sm + WS_FLOATS;        // [2][196*8]  half0 (shifted: slot tt = P1[t=tt-1])
    float* psB = psA + PS_FLOATS;       // [2][196*8]  half1 (slot tt = P2[tt], slot7=0)

    int qq = blockIdx.y;
    int c0 = blockIdx.x * TCo;
    int np = blockIdx.z;
    int tid = threadIdx.x;
    int pi = qq / 14, pj = qq - pi * 14;

    // Stage P rows t-strided (both halves, both local n).
    #pragma unroll
    for (int r = 0; r < 14; r++) {
        int n_l = r / 7, t = r - n_l * 7;
        if (tid < LL) {
            int n = np * 2 + n_l;
            size_t base = ((size_t)(n * 7 + t) * LL + qq) * LL + tid;
            psA[n_l * (LL * 8) + tid * 8 + t + 1] = g_P1[base];
            psB[n_l * (LL * 8) + tid * 8 + t]     = g_P2[base];
        }
    }
    if (tid < LL) {
        psA[tid * 8] = 0.f;            psA[LL * 8 + tid * 8] = 0.f;
        psB[tid * 8 + 7] = 0.f;        psB[LL * 8 + tid * 8 + 7] = 0.f;
    }

    int wid = tid >> 5, lane = tid & 31;
    int n_l = wid >> 2, kq = wid & 3;
    // k-quarter split of 98: 25,25,24,24
    int kst = kq * 25 - ((kq > 2) ? (kq - 2) : 0);
    int kcn = 25 - (kq >= 2 ? 1 : 0);

    u64 acc[8];   // [tp][cpart]: tp = tt-pair 0..3, cpart = which of lane's 2 cols
    #pragma unroll
    for (int i = 0; i < 8; i++) acc[i] = 0ULL;

    #pragma unroll
    for (int ph = 0; ph < 4; ph++) {
        const float* w = (ph < 2) ? w1 : w2;
        const float* ps = ((ph < 2) ? psA : psB) + n_l * (LL * 8);
        int kbase = (ph & 1) * 98;

        __syncthreads();   // ws free to overwrite (and ps staged, for ph=0)
        // Gather 98 w rows (this block's 64-col slice): 16 float4 per row.
        for (int i = tid; i < 98 * 16; i += 256) {
            int kk = i >> 4, cq = i & 15;
            int kg = kbase + kk;
            int ki = kg / 14, kj = kg - ki * 14;
            int idx = (pi - ki + 13) * 27 + (pj - kj + 13);
            *(float4*)&ws[kk * TCo + cq * 4] =
                *(const float4*)(w + (size_t)idx * CC + c0 + cq * 4);
        }
        __syncthreads();

        #pragma unroll 5
        for (int kl = kst; kl < kst + kcn; kl++) {
            float2 wv = *(const float2*)&ws[kl * TCo + 2 * lane];
            u64 b0 = pk2(wv.x, wv.x), b1 = pk2(wv.y, wv.y);
            const u64* pp = (const u64*)&ps[(kbase + kl) * 8];
            u64 p0 = pp[0], p1 = pp[1], p2 = pp[2], p3 = pp[3];
            acc[0] = ffma2(p0, b0, acc[0]);  acc[1] = ffma2(p0, b1, acc[1]);
            acc[2] = ffma2(p1, b0, acc[2]);  acc[3] = ffma2(p1, b1, acc[3]);
            acc[4] = ffma2(p2, b0, acc[4]);  acc[5] = ffma2(p2, b1, acc[5]);
            acc[6] = ffma2(p3, b0, acc[6]);  acc[7] = ffma2(p3, b1, acc[7]);
        }
    }

    // Cross-k-quarter reduction through smem (reuse ws area).
    __syncthreads();
    u64* red = (u64*)ws;
    if (kq) {
        int base = ((n_l * 3 + (kq - 1)) * 32 + lane) * 8;
        #pragma unroll
        for (int j = 0; j < 8; j++) red[base + j] = acc[j];
    }
    __syncthreads();

    if (kq == 0) {
        #pragma unroll
        for (int ww = 0; ww < 3; ww++) {
            int base = ((n_l * 3 + ww) * 32 + lane) * 8;
            #pragma unroll
            for (int j = 0; j < 8; j++) acc[j] = fadd2(acc[j], red[base + j]);
        }
        int n = np * 2 + n_l;
        float a[16];
        #pragma unroll
        for (int i = 0; i < 8; i++) upk2(acc[i], a[2 * i], a[2 * i + 1]);
        #pragma unroll
        for (int tt = 0; tt < 8; tt++) {
            int tp = tt >> 1, hi = tt & 1;
            float2 o2;
            o2.x = a[(tp * 2 + 0) * 2 + hi];   // lane col 2*lane
            o2.y = a[(tp * 2 + 1) * 2 + hi];   // lane col 2*lane+1
            *(float2*)(out + ((size_t)(n * TDIM + tt) * LP1 + qq + 1) * CC
                       + c0 + 2 * lane) = o2;
        }
    }
}

// ---------------------------------------------------------------------------
extern "C" void kernel_launch(void* const* d_in, const int* in_sizes, int n_in,
                              void* d_out, int out_size) {
    const float* q  = (const float*)d_in[0];
    const float* k  = (const float*)d_in[1];
    const float* w1 = (const float*)d_in[2];
    const float* w2 = (const float*)d_in[3];
    float* out = (float*)d_out;

    cudaFuncSetAttribute(attn_kernel, cudaFuncAttributeMaxDynamicSharedMemorySize, A_SMEM_BYTES);
    cudaFuncSetAttribute(out_kernel,  cudaFuncAttributeMaxDynamicSharedMemorySize, O_SMEM_BYTES);

    zero_kernel<<<512, 256>>>(out);
    attn_kernel<<<dim3(HH, NT, 4), 256, A_SMEM_BYTES>>>(q, k);
    out_kernel<<<dim3(CC / TCo, LL, NB / 2), 256, O_SMEM_BYTES>>>(w1, w2, out);
}